// round 15
// baseline (speedup 1.0000x reference)
#include <cuda_runtime.h>
#include <cstdint>

#define NPTS 8192
#define DIM 128
#define KM1 7
#define NROWS 57344          // 7*8192
#define NBLK4 7168           // 57344/8
#define TINYF 1.17549435e-38f

// dynamic smem for k1: As(32x132) + Bs(32x132) + Wt(128x132) floats
#define K1_SMEM ((2 * 32 * 132 + 128 * 132) * 4)

// ---------------- scratch (static device globals; no allocations) ----------
__device__ unsigned long long g_cjw[(size_t)NPTS * NPTS];   // packed (W,j) lists (unordered)
__device__ int                g_cnt[NPTS];
__device__ float              g_sq[NPTS];
__device__ int                g_samp[NROWS];
__device__ double             g_ploss[NBLK4];
__device__ float              g_pcnt[NBLK4];
// opaque rotation multipliers 2^r (mutable global: ptxas must keep IMAD.WIDE)
__device__ uint32_t g_rotm[8] = {1u << 13, 1u << 15, 1u << 26, 1u << 6,
                                 1u << 17, 1u << 29, 1u << 16, 1u << 24};

// rotl(x, r) as ONE wide multiply (fma pipe) + caller fuses (lo|hi)^x0 to LOP3
__device__ __forceinline__ uint32_t rotm(uint32_t x, uint32_t m) {
    unsigned long long w;
    asm("mul.wide.u32 %0, %1, %2;" : "=l"(w) : "r"(x), "r"(m));
    return (uint32_t)w | (uint32_t)(w >> 32);
}

// ---- threefry2x32, key=(0,42), counter=(0, c1), out = o0^o1 ---------------
// Rotations ride the fma pipe as IMAD.WIDE; combine is one LOP3. Bit-exact.
__device__ __forceinline__ uint32_t tf_bits(uint32_t c1, const uint32_t* m) {
    const uint32_t k1 = 42u;
    const uint32_t k2 = 0x1BD11BDAu ^ 42u;
    uint32_t x1 = c1 + k1;
    uint32_t x0 = x1;                              // x0 was 0: round-1 add free
    x1 = rotm(x1, m[0]) ^ x0;                      // r=13
#define TFR(i) x0 += x1; x1 = rotm(x1, m[i]) ^ x0;
    TFR(1) TFR(2) TFR(3)   x0 += k1; x1 += k2 + 1u;   // r=15,26,6
    TFR(4) TFR(5) TFR(6) TFR(7)  x0 += k2; x1 += 2u;  // r=17,29,16,24
    TFR(0) TFR(1) TFR(2) TFR(3)  x1 += k1 + 3u;       // r=13,15,26,6
    TFR(4) TFR(5) TFR(6) TFR(7)  x0 += k1; x1 += k2 + 4u;
    TFR(0) TFR(1) TFR(2) TFR(3)  x0 += k2; x1 += 5u;
#undef TFR
    return x0 ^ x1;
}

// t = -log(max(f, tiny)), f in [0,1). Precise near f->1 via atanh series.
__device__ __forceinline__ float neg_log_u(float f) {
    float r  = f - 1.0f;
    float s  = __fdividef(r, 2.0f + r);
    float s2 = s * s;
    float tp = -2.0f * s * (1.0f + s2 * (0.33333334f + s2 * (0.2f + s2 * 0.14285715f)));
    float u  = fmaxf(f, TINYF);
    float tf = -__logf(u);
    return (f > 0.75f) ? tp : tf;
}

// ---------------- K0: row squared norms + zero counters ---------------------
__global__ void k0_sq(const float* __restrict__ x) {
    __shared__ float red[128];
    int i = blockIdx.x;
    float v = x[(size_t)i * DIM + threadIdx.x];
    red[threadIdx.x] = v * v;
    __syncthreads();
    for (int s = 64; s > 0; s >>= 1) {
        if (threadIdx.x < s) red[threadIdx.x] += red[threadIdx.x + s];
        __syncthreads();
    }
    if (threadIdx.x == 0) { g_sq[i] = red[0]; g_cnt[i] = 0; }
}

// ---- K1: upper-triangle gram tiles -> smem-staged coalesced compaction ----
__global__ __launch_bounds__(256) void k1_fused(const float* __restrict__ x) {
    int bx = blockIdx.x, by = blockIdx.y;
    if (bx < by) return;                           // upper triangle only
    extern __shared__ float smem[];
    float (*As)[132] = (float(*)[132])smem;
    float (*Bs)[132] = (float(*)[132])(smem + 32 * 132);
    float* Wt = smem + 2 * 32 * 132;               // 128 x 132 tile of W

    int row0 = by * 128, col0 = bx * 128;
    int t = threadIdx.x;
    float acc[8][8];
#pragma unroll
    for (int a = 0; a < 8; a++)
#pragma unroll
        for (int b = 0; b < 8; b++) acc[a][b] = 0.f;
    int tm0 = (t >> 4) * 8, tn0 = (t & 15) * 8;

    for (int kc = 0; kc < DIM; kc += 32) {
#pragma unroll
        for (int it = 0; it < 4; it++) {
            int f  = it * 256 + t;
            int r  = f >> 3;
            int c4 = (f & 7) << 2;
            float4 va = *(const float4*)(x + (size_t)(row0 + r) * DIM + kc + c4);
            As[c4][r] = va.x; As[c4 + 1][r] = va.y; As[c4 + 2][r] = va.z; As[c4 + 3][r] = va.w;
            float4 vb = *(const float4*)(x + (size_t)(col0 + r) * DIM + kc + c4);
            Bs[c4][r] = vb.x; Bs[c4 + 1][r] = vb.y; Bs[c4 + 2][r] = vb.z; Bs[c4 + 3][r] = vb.w;
        }
        __syncthreads();
#pragma unroll
        for (int k = 0; k < 32; k++) {
            float a[8], b[8];
            *(float4*)(a)     = *(const float4*)&As[k][tm0];
            *(float4*)(a + 4) = *(const float4*)&As[k][tm0 + 4];
            *(float4*)(b)     = *(const float4*)&Bs[k][tn0];
            *(float4*)(b + 4) = *(const float4*)&Bs[k][tn0 + 4];
#pragma unroll
            for (int m = 0; m < 8; m++)
#pragma unroll
                for (int n = 0; n < 8; n++)
                    acc[m][n] = fmaf(a[m], b[n], acc[m][n]);
        }
        __syncthreads();
    }

    float sqi[8], sqj[8];
#pragma unroll
    for (int m = 0; m < 8; m++) sqi[m] = g_sq[row0 + tm0 + m];
#pragma unroll
    for (int n = 0; n < 8; n++) sqj[n] = g_sq[col0 + tn0 + n];

    // masked weight -> staged tile (float4 stores, stride 132)
#pragma unroll
    for (int m = 0; m < 8; m++) {
        int i = row0 + tm0 + m, ib = i >> 3;
        float out[8];
#pragma unroll
        for (int n = 0; n < 8; n++) {
            int j = col0 + tn0 + n;
            float q  = sqi[m] + sqj[n] - 2.f * acc[m][n];
            bool val = ((j >> 3) != ib) && (q < 1.9599999f);
            float qc = fmaxf(q, 0.25f);
            float W  = __expf(fmaf(-63.f, __logf(qc), -62.5f * __logf(1.f - 0.25f * qc)));
            out[n] = val ? W : 0.f;
        }
        float4* dst = (float4*)(Wt + (tm0 + m) * 132 + tn0);
        dst[0] = *(float4*)out;
        dst[1] = *(float4*)(out + 4);
    }
    __syncthreads();

    int lane = t & 31, wid = t >> 5;

    // row-side compaction: warp w handles rows w*16..w*16+15, coalesced writes
    for (int r = wid * 16; r < wid * 16 + 16; r++) {
        int i = row0 + r;
        float wv[4]; unsigned bal[4]; int pc[4];
#pragma unroll
        for (int c = 0; c < 4; c++) {
            wv[c]  = Wt[r * 132 + c * 32 + lane];
            bal[c] = __ballot_sync(0xffffffffu, wv[c] > 0.f);
            pc[c]  = __popc(bal[c]);
        }
        int tot = pc[0] + pc[1] + pc[2] + pc[3];
        int base = 0;
        if (lane == 0 && tot) base = atomicAdd(&g_cnt[i], tot);
        base = __shfl_sync(0xffffffffu, base, 0);
        unsigned long long* dst = g_cjw + (size_t)i * NPTS;
#pragma unroll
        for (int c = 0; c < 4; c++) {
            if (wv[c] > 0.f) {
                int pre = __popc(bal[c] & ((1u << lane) - 1u));
                dst[base + pre] = ((unsigned long long)__float_as_uint(wv[c]) << 32)
                                | (unsigned)(col0 + c * 32 + lane);
            }
            base += pc[c];
        }
    }

    // mirror: columns become rows of the transposed tile (off-diagonal only)
    if (bx != by) {
        for (int cC = wid * 16; cC < wid * 16 + 16; cC++) {
            int j = col0 + cC;
            float wv[4]; unsigned bal[4]; int pc[4];
#pragma unroll
            for (int c = 0; c < 4; c++) {
                wv[c]  = Wt[(c * 32 + lane) * 132 + cC];
                bal[c] = __ballot_sync(0xffffffffu, wv[c] > 0.f);
                pc[c]  = __popc(bal[c]);
            }
            int tot = pc[0] + pc[1] + pc[2] + pc[3];
            int base = 0;
            if (lane == 0 && tot) base = atomicAdd(&g_cnt[j], tot);
            base = __shfl_sync(0xffffffffu, base, 0);
            unsigned long long* dst = g_cjw + (size_t)j * NPTS;
#pragma unroll
            for (int c = 0; c < 4; c++) {
                if (wv[c] > 0.f) {
                    int pre = __popc(bal[c] & ((1u << lane) - 1u));
                    dst[base + pre] = ((unsigned long long)__float_as_uint(wv[c]) << 32)
                                    | (unsigned)(row0 + c * 32 + lane);
                }
                base += pc[c];
            }
        }
    }
}

// ---------------- K3: 7-sample gumbel argmax per anchor ---------------------
// counter = (s*8192 + i)*8192 + j = s*2^26 + i*2^13 + j  (< 2^32)
__global__ __launch_bounds__(256) void k3_sample() {
    int i = blockIdx.x;
    int cnt = g_cnt[i];
    const unsigned long long* __restrict__ lst = g_cjw + (size_t)i * NPTS;
    unsigned base_i = (unsigned)i << 13;

    uint32_t rm[8];
#pragma unroll
    for (int q = 0; q < 8; q++) rm[q] = g_rotm[q];

    __shared__ float sv[256];
    __shared__ int   si[256];

    float bv[KM1];
    int   bj[KM1];
#pragma unroll
    for (int s = 0; s < KM1; s++) { bv[s] = -1.0f; bj[s] = 0x7FFFFFFF; }

    if (cnt > 0) {
        // ---- seed: exact path on first min(cnt,256) entries ----
        if (threadIdx.x < cnt) {
            unsigned long long e = __ldg(lst + threadIdx.x);
            unsigned j = (unsigned)e;
            float W = __uint_as_float((unsigned)(e >> 32));
            unsigned cbase = base_i + j;
#pragma unroll
            for (int s = 0; s < KM1; s++) {
                uint32_t b = tf_bits(cbase + (unsigned)s * 67108864u, rm);
                float f = __uint_as_float((b >> 9) | 0x3f800000u) - 1.0f;
                float t = neg_log_u(f);
                float v = __fdividef(W, t);
                if (v > bv[s] || (v == bv[s] && (int)j < bj[s])) { bv[s] = v; bj[s] = (int)j; }
            }
        }
        // ---- block-reduce seed and broadcast to all threads ----
#pragma unroll
        for (int s = 0; s < KM1; s++) {
            __syncthreads();
            sv[threadIdx.x] = bv[s]; si[threadIdx.x] = bj[s];
            __syncthreads();
            for (int off = 128; off > 0; off >>= 1) {
                if (threadIdx.x < off) {
                    float v = sv[threadIdx.x + off];
                    int  jj = si[threadIdx.x + off];
                    if (v > sv[threadIdx.x] || (v == sv[threadIdx.x] && jj < si[threadIdx.x])) {
                        sv[threadIdx.x] = v; si[threadIdx.x] = jj;
                    }
                }
                __syncthreads();
            }
            bv[s] = sv[0]; bj[s] = si[0];
        }
        float bvs[KM1];
#pragma unroll
        for (int s = 0; s < KM1; s++) bvs[s] = bv[s] * 0.999998f;  // accept-biased slack

        // ---- main loop: cheap bound test, warp-uniform exact fallback ----
        int nIter = (cnt + 255) >> 8;
        for (int it = 1; it < nIter; it++) {
            int p = it * 256 + threadIdx.x;
            bool act = p < cnt;
            unsigned long long e = act ? __ldg(lst + p) : 0ULL;
            unsigned j = (unsigned)e;
            float W = __uint_as_float((unsigned)(e >> 32));   // 0 when inactive
            unsigned cbase = base_i + j;
#pragma unroll
            for (int s = 0; s < KM1; s++) {
                uint32_t b = tf_bits(cbase + (unsigned)s * 67108864u, rm);
                float uf = __uint_as_float((b >> 9) | 0x3f800000u);  // 1+u in [1,2)
                float om = 2.0f - uf;                                 // 1-u, exact, > 0
                bool pass = (W >= bvs[s] * om);                       // W/(1-u) >= ~bv
                if (__any_sync(0xffffffffu, pass)) {
                    if (pass) {
                        float t = neg_log_u(uf - 1.0f);
                        float v = __fdividef(W, t);
                        if (v > bv[s] || (v == bv[s] && (int)j < bj[s])) {
                            bv[s] = v; bj[s] = (int)j; bvs[s] = v * 0.999998f;
                        }
                    }
                }
            }
        }
    } else {
        // row_ok fallback: logits all 0 -> argmax of pure gumbel (W = 1)
        for (int p = threadIdx.x; p < NPTS; p += 256) {
            unsigned cbase = base_i + (unsigned)p;
#pragma unroll
            for (int s = 0; s < KM1; s++) {
                uint32_t b = tf_bits(cbase + (unsigned)s * 67108864u, rm);
                float f = __uint_as_float((b >> 9) | 0x3f800000u) - 1.0f;
                float t = neg_log_u(f);
                float v = __fdividef(1.0f, t);
                if (v > bv[s] || (v == bv[s] && p < bj[s])) { bv[s] = v; bj[s] = p; }
            }
        }
    }

    // ---- final block reduction ----
#pragma unroll
    for (int s = 0; s < KM1; s++) {
        __syncthreads();
        sv[threadIdx.x] = bv[s]; si[threadIdx.x] = bj[s];
        __syncthreads();
        for (int off = 128; off > 0; off >>= 1) {
            if (threadIdx.x < off) {
                float v = sv[threadIdx.x + off];
                int  jj = si[threadIdx.x + off];
                if (v > sv[threadIdx.x] || (v == sv[threadIdx.x] && jj < si[threadIdx.x])) {
                    sv[threadIdx.x] = v; si[threadIdx.x] = jj;
                }
            }
            __syncthreads();
        }
        if (threadIdx.x == 0) g_samp[s * NPTS + i] = si[0];
    }
}

// ---------------- K4: triplet losses, one warp per pair ---------------------
__global__ __launch_bounds__(256) void k4_pairs(const float* __restrict__ x,
                                                const float* __restrict__ beta) {
    int wid  = threadIdx.x >> 5;
    int lane = threadIdx.x & 31;
    int pair = blockIdx.x * 8 + wid;          // < 57344
    int i = pair / 7;
    int s = pair - i * 7;
    int ii = i & 7;
    int p  = (i & ~7) + (s < ii ? s : s + 1); // positives in block order, self excluded
    int nn = g_samp[s * NPTS + i];            // samples.T.reshape(-1)

    const float4* xa = (const float4*)(x + (size_t)i  * DIM);
    const float4* xp = (const float4*)(x + (size_t)p  * DIM);
    const float4* xn = (const float4*)(x + (size_t)nn * DIM);
    float4 a = xa[lane], pv = xp[lane], nv = xn[lane];
    float dap = (a.x - pv.x) * (a.x - pv.x) + (a.y - pv.y) * (a.y - pv.y)
              + (a.z - pv.z) * (a.z - pv.z) + (a.w - pv.w) * (a.w - pv.w);
    float dan = (a.x - nv.x) * (a.x - nv.x) + (a.y - nv.y) * (a.y - nv.y)
              + (a.z - nv.z) * (a.z - nv.z) + (a.w - nv.w) * (a.w - nv.w);
    for (int off = 16; off; off >>= 1) {
        dap += __shfl_down_sync(0xffffffffu, dap, off);
        dan += __shfl_down_sync(0xffffffffu, dan, off);
    }

    __shared__ double sl[8];
    __shared__ float  sc[8];
    if (lane == 0) {
        float b    = beta[i];
        float d_ap = sqrtf(dap + 1e-8f);
        float d_an = sqrtf(dan + 1e-8f);
        float pos  = fmaxf(d_ap - b + 0.2f, 0.f);
        float neg  = fmaxf(b - d_an + 0.2f, 0.f);
        sl[wid] = (double)(pos + neg);
        sc[wid] = (pos > 0.f ? 1.f : 0.f) + (neg > 0.f ? 1.f : 0.f);
    }
    __syncthreads();
    if (threadIdx.x == 0) {
        double L = 0; float C = 0;
        for (int w = 0; w < 8; w++) { L += sl[w]; C += sc[w]; }
        g_ploss[blockIdx.x] = L;
        g_pcnt[blockIdx.x]  = C;
    }
}

// ---------------- K5: deterministic final reduction --------------------------
__global__ void k5_final(float* out) {
    __shared__ double sd[256];
    __shared__ float  scn[256];
    double L = 0; float C = 0;
    for (int idx = threadIdx.x; idx < NBLK4; idx += 256) {
        L += g_ploss[idx];
        C += g_pcnt[idx];
    }
    sd[threadIdx.x] = L; scn[threadIdx.x] = C;
    __syncthreads();
    for (int s = 128; s > 0; s >>= 1) {
        if (threadIdx.x < s) {
            sd[threadIdx.x]  += sd[threadIdx.x + s];
            scn[threadIdx.x] += scn[threadIdx.x + s];
        }
        __syncthreads();
    }
    if (threadIdx.x == 0) out[0] = (float)(sd[0] / (double)scn[0]);
}

// ---------------- launch (serial, proven R6 structure) -----------------------
extern "C" void kernel_launch(void* const* d_in, const int* in_sizes, int n_in,
                              void* d_out, int out_size) {
    const float* x    = (const float*)d_in[0];   // [8192,128] f32
    const float* beta = (const float*)d_in[2];   // [8192] f32 (d_in[1] = y, unused)

    cudaFuncSetAttribute(k1_fused, cudaFuncAttributeMaxDynamicSharedMemorySize, K1_SMEM);

    k0_sq<<<NPTS, 128>>>(x);
    dim3 g1(64, 64);
    k1_fused<<<g1, 256, K1_SMEM>>>(x);
    k3_sample<<<NPTS, 256>>>();
    k4_pairs<<<NBLK4, 256>>>(x, beta);
    k5_final<<<1, 256>>>((float*)d_out);
}

// round 16
// speedup vs baseline: 1.1557x; 1.1557x over previous
#include <cuda_runtime.h>
#include <cstdint>

#define NPTS 8192
#define DIM 128
#define KM1 7
#define NROWS 57344          // 7*8192
#define NBLK4 7168           // 57344/8
#define TINYF 1.17549435e-38f

// dynamic smem for k1: As(32x132) + Bs(32x132) + Wt(128x132) floats
#define K1_SMEM ((2 * 32 * 132 + 128 * 132) * 4)

// ---------------- scratch (static device globals; no allocations) ----------
__device__ unsigned long long g_cjw[(size_t)NPTS * NPTS];   // packed (W,j) lists (unordered)
__device__ int                g_cnt[NPTS];
__device__ float              g_sq[NPTS];
__device__ int                g_samp[NROWS];
__device__ double             g_ploss[NBLK4];
__device__ float              g_pcnt[NBLK4];

// ---- threefry2x32, key=(0,42), counter=(0, c1), out = o0^o1 ---------------
__device__ __forceinline__ uint32_t tf_bits(uint32_t c1) {
    const uint32_t k1 = 42u;
    const uint32_t k2 = 0x1BD11BDAu ^ 42u;
    uint32_t x1 = c1 + k1;
    uint32_t x0 = x1;                              // x0 was 0: round-1 add free
    x1 = __funnelshift_l(x1, x1, 13) ^ x0;
#define TFR(r) x0 += x1; x1 = __funnelshift_l(x1, x1, r) ^ x0;
    TFR(15) TFR(26) TFR(6)   x0 += k1; x1 += k2 + 1u;
    TFR(17) TFR(29) TFR(16) TFR(24)  x0 += k2; x1 += 2u;
    TFR(13) TFR(15) TFR(26) TFR(6)   x1 += k1 + 3u;
    TFR(17) TFR(29) TFR(16) TFR(24)  x0 += k1; x1 += k2 + 4u;
    TFR(13) TFR(15) TFR(26) TFR(6)   x0 += k2; x1 += 5u;
#undef TFR
    return x0 ^ x1;
}

// t = -log(max(f, tiny)), f in [0,1). Precise near f->1 via atanh series.
__device__ __forceinline__ float neg_log_u(float f) {
    float r  = f - 1.0f;
    float s  = __fdividef(r, 2.0f + r);
    float s2 = s * s;
    float tp = -2.0f * s * (1.0f + s2 * (0.33333334f + s2 * (0.2f + s2 * 0.14285715f)));
    float u  = fmaxf(f, TINYF);
    float tf = -__logf(u);
    return (f > 0.75f) ? tp : tf;
}

// ---------------- K0: row squared norms + zero counters ---------------------
__global__ void k0_sq(const float* __restrict__ x) {
    __shared__ float red[128];
    int i = blockIdx.x;
    float v = x[(size_t)i * DIM + threadIdx.x];
    red[threadIdx.x] = v * v;
    __syncthreads();
    for (int s = 64; s > 0; s >>= 1) {
        if (threadIdx.x < s) red[threadIdx.x] += red[threadIdx.x + s];
        __syncthreads();
    }
    if (threadIdx.x == 0) { g_sq[i] = red[0]; g_cnt[i] = 0; }
}

// ---- K1: upper-triangle gram tiles -> smem-staged coalesced compaction ----
__global__ __launch_bounds__(256) void k1_fused(const float* __restrict__ x) {
    int bx = blockIdx.x, by = blockIdx.y;
    if (bx < by) return;                           // upper triangle only
    extern __shared__ float smem[];
    float (*As)[132] = (float(*)[132])smem;
    float (*Bs)[132] = (float(*)[132])(smem + 32 * 132);
    float* Wt = smem + 2 * 32 * 132;               // 128 x 132 tile of W

    int row0 = by * 128, col0 = bx * 128;
    int t = threadIdx.x;
    float acc[8][8];
#pragma unroll
    for (int a = 0; a < 8; a++)
#pragma unroll
        for (int b = 0; b < 8; b++) acc[a][b] = 0.f;
    int tm0 = (t >> 4) * 8, tn0 = (t & 15) * 8;

    for (int kc = 0; kc < DIM; kc += 32) {
#pragma unroll
        for (int it = 0; it < 4; it++) {
            int f  = it * 256 + t;
            int r  = f >> 3;
            int c4 = (f & 7) << 2;
            float4 va = *(const float4*)(x + (size_t)(row0 + r) * DIM + kc + c4);
            As[c4][r] = va.x; As[c4 + 1][r] = va.y; As[c4 + 2][r] = va.z; As[c4 + 3][r] = va.w;
            float4 vb = *(const float4*)(x + (size_t)(col0 + r) * DIM + kc + c4);
            Bs[c4][r] = vb.x; Bs[c4 + 1][r] = vb.y; Bs[c4 + 2][r] = vb.z; Bs[c4 + 3][r] = vb.w;
        }
        __syncthreads();
#pragma unroll
        for (int k = 0; k < 32; k++) {
            float a[8], b[8];
            *(float4*)(a)     = *(const float4*)&As[k][tm0];
            *(float4*)(a + 4) = *(const float4*)&As[k][tm0 + 4];
            *(float4*)(b)     = *(const float4*)&Bs[k][tn0];
            *(float4*)(b + 4) = *(const float4*)&Bs[k][tn0 + 4];
#pragma unroll
            for (int m = 0; m < 8; m++)
#pragma unroll
                for (int n = 0; n < 8; n++)
                    acc[m][n] = fmaf(a[m], b[n], acc[m][n]);
        }
        __syncthreads();
    }

    float sqi[8], sqj[8];
#pragma unroll
    for (int m = 0; m < 8; m++) sqi[m] = g_sq[row0 + tm0 + m];
#pragma unroll
    for (int n = 0; n < 8; n++) sqj[n] = g_sq[col0 + tn0 + n];

    // masked weight -> staged tile (float4 stores, stride 132)
#pragma unroll
    for (int m = 0; m < 8; m++) {
        int i = row0 + tm0 + m, ib = i >> 3;
        float out[8];
#pragma unroll
        for (int n = 0; n < 8; n++) {
            int j = col0 + tn0 + n;
            float q  = sqi[m] + sqj[n] - 2.f * acc[m][n];
            bool val = ((j >> 3) != ib) && (q < 1.9599999f);
            float qc = fmaxf(q, 0.25f);
            float W  = __expf(fmaf(-63.f, __logf(qc), -62.5f * __logf(1.f - 0.25f * qc)));
            out[n] = val ? W : 0.f;
        }
        float4* dst = (float4*)(Wt + (tm0 + m) * 132 + tn0);
        dst[0] = *(float4*)out;
        dst[1] = *(float4*)(out + 4);
    }
    __syncthreads();

    int lane = t & 31, wid = t >> 5;

    // row-side compaction: warp w handles rows w*16..w*16+15, coalesced writes
    for (int r = wid * 16; r < wid * 16 + 16; r++) {
        int i = row0 + r;
        float wv[4]; unsigned bal[4]; int pc[4];
#pragma unroll
        for (int c = 0; c < 4; c++) {
            wv[c]  = Wt[r * 132 + c * 32 + lane];
            bal[c] = __ballot_sync(0xffffffffu, wv[c] > 0.f);
            pc[c]  = __popc(bal[c]);
        }
        int tot = pc[0] + pc[1] + pc[2] + pc[3];
        int base = 0;
        if (lane == 0 && tot) base = atomicAdd(&g_cnt[i], tot);
        base = __shfl_sync(0xffffffffu, base, 0);
        unsigned long long* dst = g_cjw + (size_t)i * NPTS;
#pragma unroll
        for (int c = 0; c < 4; c++) {
            if (wv[c] > 0.f) {
                int pre = __popc(bal[c] & ((1u << lane) - 1u));
                dst[base + pre] = ((unsigned long long)__float_as_uint(wv[c]) << 32)
                                | (unsigned)(col0 + c * 32 + lane);
            }
            base += pc[c];
        }
    }

    // mirror: columns become rows of the transposed tile (off-diagonal only)
    if (bx != by) {
        for (int cC = wid * 16; cC < wid * 16 + 16; cC++) {
            int j = col0 + cC;
            float wv[4]; unsigned bal[4]; int pc[4];
#pragma unroll
            for (int c = 0; c < 4; c++) {
                wv[c]  = Wt[(c * 32 + lane) * 132 + cC];
                bal[c] = __ballot_sync(0xffffffffu, wv[c] > 0.f);
                pc[c]  = __popc(bal[c]);
            }
            int tot = pc[0] + pc[1] + pc[2] + pc[3];
            int base = 0;
            if (lane == 0 && tot) base = atomicAdd(&g_cnt[j], tot);
            base = __shfl_sync(0xffffffffu, base, 0);
            unsigned long long* dst = g_cjw + (size_t)j * NPTS;
#pragma unroll
            for (int c = 0; c < 4; c++) {
                if (wv[c] > 0.f) {
                    int pre = __popc(bal[c] & ((1u << lane) - 1u));
                    dst[base + pre] = ((unsigned long long)__float_as_uint(wv[c]) << 32)
                                    | (unsigned)(row0 + c * 32 + lane);
                }
                base += pc[c];
            }
        }
    }
}

// ---------------- K3: 7-sample gumbel argmax per anchor ---------------------
// counter = (s*8192 + i)*8192 + j = s*2^26 + i*2^13 + j  (< 2^32)
__global__ __launch_bounds__(256) void k3_sample() {
    int i = blockIdx.x;
    int cnt = g_cnt[i];
    const unsigned long long* __restrict__ lst = g_cjw + (size_t)i * NPTS;
    unsigned base_i = (unsigned)i << 13;

    __shared__ float sv[256];
    __shared__ int   si[256];

    float bv[KM1];
    int   bj[KM1];
#pragma unroll
    for (int s = 0; s < KM1; s++) { bv[s] = -1.0f; bj[s] = 0x7FFFFFFF; }

    if (cnt > 0) {
        // ---- seed: exact path on first min(cnt,256) entries ----
        if (threadIdx.x < cnt) {
            unsigned long long e = __ldg(lst + threadIdx.x);
            unsigned j = (unsigned)e;
            float W = __uint_as_float((unsigned)(e >> 32));
            unsigned cbase = base_i + j;
#pragma unroll
            for (int s = 0; s < KM1; s++) {
                uint32_t b = tf_bits(cbase + (unsigned)s * 67108864u);
                float f = __uint_as_float((b >> 9) | 0x3f800000u) - 1.0f;
                float t = neg_log_u(f);
                float v = __fdividef(W, t);
                if (v > bv[s] || (v == bv[s] && (int)j < bj[s])) { bv[s] = v; bj[s] = (int)j; }
            }
        }
        // ---- block-reduce seed and broadcast to all threads ----
#pragma unroll
        for (int s = 0; s < KM1; s++) {
            __syncthreads();
            sv[threadIdx.x] = bv[s]; si[threadIdx.x] = bj[s];
            __syncthreads();
            for (int off = 128; off > 0; off >>= 1) {
                if (threadIdx.x < off) {
                    float v = sv[threadIdx.x + off];
                    int  jj = si[threadIdx.x + off];
                    if (v > sv[threadIdx.x] || (v == sv[threadIdx.x] && jj < si[threadIdx.x])) {
                        sv[threadIdx.x] = v; si[threadIdx.x] = jj;
                    }
                }
                __syncthreads();
            }
            bv[s] = sv[0]; bj[s] = si[0];
        }
        float bvs[KM1];
#pragma unroll
        for (int s = 0; s < KM1; s++) bvs[s] = bv[s] * 0.999998f;  // accept-biased slack

        // ---- main loop: cheap bound test, warp-uniform exact fallback ----
        int nIter = (cnt + 255) >> 8;
        for (int it = 1; it < nIter; it++) {
            int p = it * 256 + threadIdx.x;
            bool act = p < cnt;
            unsigned long long e = act ? __ldg(lst + p) : 0ULL;
            unsigned j = (unsigned)e;
            float W = __uint_as_float((unsigned)(e >> 32));   // 0 when inactive
            unsigned cbase = base_i + j;
#pragma unroll
            for (int s = 0; s < KM1; s++) {
                uint32_t b = tf_bits(cbase + (unsigned)s * 67108864u);
                float uf = __uint_as_float((b >> 9) | 0x3f800000u);  // 1+u in [1,2)
                float om = 2.0f - uf;                                 // 1-u, exact, > 0
                bool pass = (W >= bvs[s] * om);                       // W/(1-u) >= ~bv
                if (__any_sync(0xffffffffu, pass)) {
                    if (pass) {
                        float t = neg_log_u(uf - 1.0f);
                        float v = __fdividef(W, t);
                        if (v > bv[s] || (v == bv[s] && (int)j < bj[s])) {
                            bv[s] = v; bj[s] = (int)j; bvs[s] = v * 0.999998f;
                        }
                    }
                }
            }
        }
    } else {
        // row_ok fallback: logits all 0 -> argmax of pure gumbel (W = 1)
        for (int p = threadIdx.x; p < NPTS; p += 256) {
            unsigned cbase = base_i + (unsigned)p;
#pragma unroll
            for (int s = 0; s < KM1; s++) {
                uint32_t b = tf_bits(cbase + (unsigned)s * 67108864u);
                float f = __uint_as_float((b >> 9) | 0x3f800000u) - 1.0f;
                float t = neg_log_u(f);
                float v = __fdividef(1.0f, t);
                if (v > bv[s] || (v == bv[s] && p < bj[s])) { bv[s] = v; bj[s] = p; }
            }
        }
    }

    // ---- final block reduction ----
#pragma unroll
    for (int s = 0; s < KM1; s++) {
        __syncthreads();
        sv[threadIdx.x] = bv[s]; si[threadIdx.x] = bj[s];
        __syncthreads();
        for (int off = 128; off > 0; off >>= 1) {
            if (threadIdx.x < off) {
                float v = sv[threadIdx.x + off];
                int  jj = si[threadIdx.x + off];
                if (v > sv[threadIdx.x] || (v == sv[threadIdx.x] && jj < si[threadIdx.x])) {
                    sv[threadIdx.x] = v; si[threadIdx.x] = jj;
                }
            }
            __syncthreads();
        }
        if (threadIdx.x == 0) g_samp[s * NPTS + i] = si[0];
    }
}

// ---------------- K4: triplet losses, one warp per pair ---------------------
__global__ __launch_bounds__(256) void k4_pairs(const float* __restrict__ x,
                                                const float* __restrict__ beta) {
    int wid  = threadIdx.x >> 5;
    int lane = threadIdx.x & 31;
    int pair = blockIdx.x * 8 + wid;          // < 57344
    int i = pair / 7;
    int s = pair - i * 7;
    int ii = i & 7;
    int p  = (i & ~7) + (s < ii ? s : s + 1); // positives in block order, self excluded
    int nn = g_samp[s * NPTS + i];            // samples.T.reshape(-1)

    const float4* xa = (const float4*)(x + (size_t)i  * DIM);
    const float4* xp = (const float4*)(x + (size_t)p  * DIM);
    const float4* xn = (const float4*)(x + (size_t)nn * DIM);
    float4 a = xa[lane], pv = xp[lane], nv = xn[lane];
    float dap = (a.x - pv.x) * (a.x - pv.x) + (a.y - pv.y) * (a.y - pv.y)
              + (a.z - pv.z) * (a.z - pv.z) + (a.w - pv.w) * (a.w - pv.w);
    float dan = (a.x - nv.x) * (a.x - nv.x) + (a.y - nv.y) * (a.y - nv.y)
              + (a.z - nv.z) * (a.z - nv.z) + (a.w - nv.w) * (a.w - nv.w);
    for (int off = 16; off; off >>= 1) {
        dap += __shfl_down_sync(0xffffffffu, dap, off);
        dan += __shfl_down_sync(0xffffffffu, dan, off);
    }

    __shared__ double sl[8];
    __shared__ float  sc[8];
    if (lane == 0) {
        float b    = beta[i];
        float d_ap = sqrtf(dap + 1e-8f);
        float d_an = sqrtf(dan + 1e-8f);
        float pos  = fmaxf(d_ap - b + 0.2f, 0.f);
        float neg  = fmaxf(b - d_an + 0.2f, 0.f);
        sl[wid] = (double)(pos + neg);
        sc[wid] = (pos > 0.f ? 1.f : 0.f) + (neg > 0.f ? 1.f : 0.f);
    }
    __syncthreads();
    if (threadIdx.x == 0) {
        double L = 0; float C = 0;
        for (int w = 0; w < 8; w++) { L += sl[w]; C += sc[w]; }
        g_ploss[blockIdx.x] = L;
        g_pcnt[blockIdx.x]  = C;
    }
}

// ---------------- K5: deterministic final reduction --------------------------
__global__ void k5_final(float* out) {
    __shared__ double sd[256];
    __shared__ float  scn[256];
    double L = 0; float C = 0;
    for (int idx = threadIdx.x; idx < NBLK4; idx += 256) {
        L += g_ploss[idx];
        C += g_pcnt[idx];
    }
    sd[threadIdx.x] = L; scn[threadIdx.x] = C;
    __syncthreads();
    for (int s = 128; s > 0; s >>= 1) {
        if (threadIdx.x < s) {
            sd[threadIdx.x]  += sd[threadIdx.x + s];
            scn[threadIdx.x] += scn[threadIdx.x + s];
        }
        __syncthreads();
    }
    if (threadIdx.x == 0) out[0] = (float)(sd[0] / (double)scn[0]);
}

// ---------------- launch (serial, proven R6 structure) -----------------------
extern "C" void kernel_launch(void* const* d_in, const int* in_sizes, int n_in,
                              void* d_out, int out_size) {
    const float* x    = (const float*)d_in[0];   // [8192,128] f32
    const float* beta = (const float*)d_in[2];   // [8192] f32 (d_in[1] = y, unused)

    cudaFuncSetAttribute(k1_fused, cudaFuncAttributeMaxDynamicSharedMemorySize, K1_SMEM);

    k0_sq<<<NPTS, 128>>>(x);
    dim3 g1(64, 64);
    k1_fused<<<g1, 256, K1_SMEM>>>(x);
    k3_sample<<<NPTS, 256>>>();
    k4_pairs<<<NBLK4, 256>>>(x, beta);
    k5_final<<<1, 256>>>((float*)d_out);
}

// round 17
// speedup vs baseline: 1.1620x; 1.0055x over previous
#include <cuda_runtime.h>
#include <cstdint>

#define NPTS 8192
#define DIM 128
#define KM1 7
#define NROWS 57344          // 7*8192
#define NBLK4 7168           // 57344/8
#define TINYF 1.17549435e-38f

// dynamic smem for k1: As(32x132) + Bs(32x132) + Wt(128x132) floats
#define K1_SMEM ((2 * 32 * 132 + 128 * 132) * 4)

// ---------------- scratch (static device globals; no allocations) ----------
__device__ unsigned long long g_cjw[(size_t)NPTS * NPTS];   // packed (W,j) lists (unordered)
__device__ int                g_cnt[NPTS];
__device__ float              g_sq[NPTS];
__device__ int                g_samp[NROWS];
__device__ double             g_ploss[NBLK4];
__device__ float              g_pcnt[NBLK4];

// ---- threefry2x32, key=(0,42), counter=(0, c1), out = o0^o1 ---------------
__device__ __forceinline__ uint32_t tf_bits(uint32_t c1) {
    const uint32_t k1 = 42u;
    const uint32_t k2 = 0x1BD11BDAu ^ 42u;
    uint32_t x1 = c1 + k1;
    uint32_t x0 = x1;                              // x0 was 0: round-1 add free
    x1 = __funnelshift_l(x1, x1, 13) ^ x0;
#define TFR(r) x0 += x1; x1 = __funnelshift_l(x1, x1, r) ^ x0;
    TFR(15) TFR(26) TFR(6)   x0 += k1; x1 += k2 + 1u;
    TFR(17) TFR(29) TFR(16) TFR(24)  x0 += k2; x1 += 2u;
    TFR(13) TFR(15) TFR(26) TFR(6)   x1 += k1 + 3u;
    TFR(17) TFR(29) TFR(16) TFR(24)  x0 += k1; x1 += k2 + 4u;
    TFR(13) TFR(15) TFR(26) TFR(6)   x0 += k2; x1 += 5u;
#undef TFR
    return x0 ^ x1;
}

// t = -log(max(f, tiny)), f in [0,1). Precise near f->1 via atanh series.
__device__ __forceinline__ float neg_log_u(float f) {
    float r  = f - 1.0f;
    float s  = __fdividef(r, 2.0f + r);
    float s2 = s * s;
    float tp = -2.0f * s * (1.0f + s2 * (0.33333334f + s2 * (0.2f + s2 * 0.14285715f)));
    float u  = fmaxf(f, TINYF);
    float tf = -__logf(u);
    return (f > 0.75f) ? tp : tf;
}

// warp-butterfly lexicographic max: (v desc, j asc). All lanes converge.
__device__ __forceinline__ void warp_red(float& v, int& j) {
#pragma unroll
    for (int off = 16; off; off >>= 1) {
        float v2 = __shfl_xor_sync(0xffffffffu, v, off);
        int   j2 = __shfl_xor_sync(0xffffffffu, j, off);
        if (v2 > v || (v2 == v && j2 < j)) { v = v2; j = j2; }
    }
}

// ---------------- K0: row squared norms + zero counters ---------------------
__global__ void k0_sq(const float* __restrict__ x) {
    __shared__ float red[128];
    int i = blockIdx.x;
    float v = x[(size_t)i * DIM + threadIdx.x];
    red[threadIdx.x] = v * v;
    __syncthreads();
    for (int s = 64; s > 0; s >>= 1) {
        if (threadIdx.x < s) red[threadIdx.x] += red[threadIdx.x + s];
        __syncthreads();
    }
    if (threadIdx.x == 0) { g_sq[i] = red[0]; g_cnt[i] = 0; }
}

// ---- K1: upper-triangle gram tiles -> smem-staged coalesced compaction ----
__global__ __launch_bounds__(256) void k1_fused(const float* __restrict__ x) {
    int bx = blockIdx.x, by = blockIdx.y;
    if (bx < by) return;                           // upper triangle only
    extern __shared__ float smem[];
    float (*As)[132] = (float(*)[132])smem;
    float (*Bs)[132] = (float(*)[132])(smem + 32 * 132);
    float* Wt = smem + 2 * 32 * 132;               // 128 x 132 tile of W

    int row0 = by * 128, col0 = bx * 128;
    int t = threadIdx.x;
    float acc[8][8];
#pragma unroll
    for (int a = 0; a < 8; a++)
#pragma unroll
        for (int b = 0; b < 8; b++) acc[a][b] = 0.f;
    int tm0 = (t >> 4) * 8, tn0 = (t & 15) * 8;

    for (int kc = 0; kc < DIM; kc += 32) {
#pragma unroll
        for (int it = 0; it < 4; it++) {
            int f  = it * 256 + t;
            int r  = f >> 3;
            int c4 = (f & 7) << 2;
            float4 va = *(const float4*)(x + (size_t)(row0 + r) * DIM + kc + c4);
            As[c4][r] = va.x; As[c4 + 1][r] = va.y; As[c4 + 2][r] = va.z; As[c4 + 3][r] = va.w;
            float4 vb = *(const float4*)(x + (size_t)(col0 + r) * DIM + kc + c4);
            Bs[c4][r] = vb.x; Bs[c4 + 1][r] = vb.y; Bs[c4 + 2][r] = vb.z; Bs[c4 + 3][r] = vb.w;
        }
        __syncthreads();
#pragma unroll
        for (int k = 0; k < 32; k++) {
            float a[8], b[8];
            *(float4*)(a)     = *(const float4*)&As[k][tm0];
            *(float4*)(a + 4) = *(const float4*)&As[k][tm0 + 4];
            *(float4*)(b)     = *(const float4*)&Bs[k][tn0];
            *(float4*)(b + 4) = *(const float4*)&Bs[k][tn0 + 4];
#pragma unroll
            for (int m = 0; m < 8; m++)
#pragma unroll
                for (int n = 0; n < 8; n++)
                    acc[m][n] = fmaf(a[m], b[n], acc[m][n]);
        }
        __syncthreads();
    }

    float sqi[8], sqj[8];
#pragma unroll
    for (int m = 0; m < 8; m++) sqi[m] = g_sq[row0 + tm0 + m];
#pragma unroll
    for (int n = 0; n < 8; n++) sqj[n] = g_sq[col0 + tn0 + n];

    // masked weight -> staged tile (float4 stores, stride 132)
#pragma unroll
    for (int m = 0; m < 8; m++) {
        int i = row0 + tm0 + m, ib = i >> 3;
        float out[8];
#pragma unroll
        for (int n = 0; n < 8; n++) {
            int j = col0 + tn0 + n;
            float q  = sqi[m] + sqj[n] - 2.f * acc[m][n];
            bool val = ((j >> 3) != ib) && (q < 1.9599999f);
            float qc = fmaxf(q, 0.25f);
            float W  = __expf(fmaf(-63.f, __logf(qc), -62.5f * __logf(1.f - 0.25f * qc)));
            out[n] = val ? W : 0.f;
        }
        float4* dst = (float4*)(Wt + (tm0 + m) * 132 + tn0);
        dst[0] = *(float4*)out;
        dst[1] = *(float4*)(out + 4);
    }
    __syncthreads();

    int lane = t & 31, wid = t >> 5;

    // row-side compaction: warp w handles rows w*16..w*16+15, coalesced writes
    for (int r = wid * 16; r < wid * 16 + 16; r++) {
        int i = row0 + r;
        float wv[4]; unsigned bal[4]; int pc[4];
#pragma unroll
        for (int c = 0; c < 4; c++) {
            wv[c]  = Wt[r * 132 + c * 32 + lane];
            bal[c] = __ballot_sync(0xffffffffu, wv[c] > 0.f);
            pc[c]  = __popc(bal[c]);
        }
        int tot = pc[0] + pc[1] + pc[2] + pc[3];
        int base = 0;
        if (lane == 0 && tot) base = atomicAdd(&g_cnt[i], tot);
        base = __shfl_sync(0xffffffffu, base, 0);
        unsigned long long* dst = g_cjw + (size_t)i * NPTS;
#pragma unroll
        for (int c = 0; c < 4; c++) {
            if (wv[c] > 0.f) {
                int pre = __popc(bal[c] & ((1u << lane) - 1u));
                dst[base + pre] = ((unsigned long long)__float_as_uint(wv[c]) << 32)
                                | (unsigned)(col0 + c * 32 + lane);
            }
            base += pc[c];
        }
    }

    // mirror: columns become rows of the transposed tile (off-diagonal only)
    if (bx != by) {
        for (int cC = wid * 16; cC < wid * 16 + 16; cC++) {
            int j = col0 + cC;
            float wv[4]; unsigned bal[4]; int pc[4];
#pragma unroll
            for (int c = 0; c < 4; c++) {
                wv[c]  = Wt[(c * 32 + lane) * 132 + cC];
                bal[c] = __ballot_sync(0xffffffffu, wv[c] > 0.f);
                pc[c]  = __popc(bal[c]);
            }
            int tot = pc[0] + pc[1] + pc[2] + pc[3];
            int base = 0;
            if (lane == 0 && tot) base = atomicAdd(&g_cnt[j], tot);
            base = __shfl_sync(0xffffffffu, base, 0);
            unsigned long long* dst = g_cjw + (size_t)j * NPTS;
#pragma unroll
            for (int c = 0; c < 4; c++) {
                if (wv[c] > 0.f) {
                    int pre = __popc(bal[c] & ((1u << lane) - 1u));
                    dst[base + pre] = ((unsigned long long)__float_as_uint(wv[c]) << 32)
                                    | (unsigned)(row0 + c * 32 + lane);
                }
                base += pc[c];
            }
        }
    }
}

// ---------------- K3: 7-sample gumbel argmax per anchor ---------------------
// counter = (s*8192 + i)*8192 + j = s*2^26 + i*2^13 + j  (< 2^32)
// Main loop identical to the champion; block reductions replaced by
// shuffle-butterfly + one smem round (2 barriers total instead of 224).
__global__ __launch_bounds__(256) void k3_sample() {
    int i = blockIdx.x;
    int cnt = g_cnt[i];
    const unsigned long long* __restrict__ lst = g_cjw + (size_t)i * NPTS;
    unsigned base_i = (unsigned)i << 13;

    __shared__ float wsv[KM1][8];
    __shared__ int   wsi[KM1][8];

    int lane = threadIdx.x & 31, wid = threadIdx.x >> 5;

    float bv[KM1];
    int   bj[KM1];
#pragma unroll
    for (int s = 0; s < KM1; s++) { bv[s] = -1.0f; bj[s] = 0x7FFFFFFF; }

    if (cnt > 0) {
        // ---- seed: exact path on first min(cnt,256) entries ----
        if (threadIdx.x < cnt) {
            unsigned long long e = __ldg(lst + threadIdx.x);
            unsigned j = (unsigned)e;
            float W = __uint_as_float((unsigned)(e >> 32));
            unsigned cbase = base_i + j;
#pragma unroll
            for (int s = 0; s < KM1; s++) {
                uint32_t b = tf_bits(cbase + (unsigned)s * 67108864u);
                float f = __uint_as_float((b >> 9) | 0x3f800000u) - 1.0f;
                float t = neg_log_u(f);
                float v = __fdividef(W, t);
                if (v > bv[s] || (v == bv[s] && (int)j < bj[s])) { bv[s] = v; bj[s] = (int)j; }
            }
        }
        // ---- block-reduce seed (warp butterfly + one smem round) ----
#pragma unroll
        for (int s = 0; s < KM1; s++) {
            warp_red(bv[s], bj[s]);
            if (lane == 0) { wsv[s][wid] = bv[s]; wsi[s][wid] = bj[s]; }
        }
        __syncthreads();
#pragma unroll
        for (int s = 0; s < KM1; s++) {
            float v = wsv[s][0]; int j = wsi[s][0];
#pragma unroll
            for (int w = 1; w < 8; w++) {
                float v2 = wsv[s][w]; int j2 = wsi[s][w];
                if (v2 > v || (v2 == v && j2 < j)) { v = v2; j = j2; }
            }
            bv[s] = v; bj[s] = j;                  // broadcast to all threads
        }
        float bvs[KM1];
#pragma unroll
        for (int s = 0; s < KM1; s++) bvs[s] = bv[s] * 0.999998f;  // accept-biased slack

        // ---- main loop: cheap bound test, warp-uniform exact fallback ----
        int nIter = (cnt + 255) >> 8;
        for (int it = 1; it < nIter; it++) {
            int p = it * 256 + threadIdx.x;
            bool act = p < cnt;
            unsigned long long e = act ? __ldg(lst + p) : 0ULL;
            unsigned j = (unsigned)e;
            float W = __uint_as_float((unsigned)(e >> 32));   // 0 when inactive
            unsigned cbase = base_i + j;
#pragma unroll
            for (int s = 0; s < KM1; s++) {
                uint32_t b = tf_bits(cbase + (unsigned)s * 67108864u);
                float uf = __uint_as_float((b >> 9) | 0x3f800000u);  // 1+u in [1,2)
                float om = 2.0f - uf;                                 // 1-u, exact, > 0
                bool pass = (W >= bvs[s] * om);                       // W/(1-u) >= ~bv
                if (__any_sync(0xffffffffu, pass)) {
                    if (pass) {
                        float t = neg_log_u(uf - 1.0f);
                        float v = __fdividef(W, t);
                        if (v > bv[s] || (v == bv[s] && (int)j < bj[s])) {
                            bv[s] = v; bj[s] = (int)j; bvs[s] = v * 0.999998f;
                        }
                    }
                }
            }
        }
    } else {
        // row_ok fallback: logits all 0 -> argmax of pure gumbel (W = 1)
        for (int p = threadIdx.x; p < NPTS; p += 256) {
            unsigned cbase = base_i + (unsigned)p;
#pragma unroll
            for (int s = 0; s < KM1; s++) {
                uint32_t b = tf_bits(cbase + (unsigned)s * 67108864u);
                float f = __uint_as_float((b >> 9) | 0x3f800000u) - 1.0f;
                float t = neg_log_u(f);
                float v = __fdividef(1.0f, t);
                if (v > bv[s] || (v == bv[s] && p < bj[s])) { bv[s] = v; bj[s] = p; }
            }
        }
    }

    // ---- final block reduction (warp butterfly + one smem round) ----
    __syncthreads();                               // protect wsv/wsi reuse
#pragma unroll
    for (int s = 0; s < KM1; s++) {
        warp_red(bv[s], bj[s]);
        if (lane == 0) { wsv[s][wid] = bv[s]; wsi[s][wid] = bj[s]; }
    }
    __syncthreads();
    if (threadIdx.x < KM1) {
        int s = threadIdx.x;
        float v = wsv[s][0]; int j = wsi[s][0];
#pragma unroll
        for (int w = 1; w < 8; w++) {
            float v2 = wsv[s][w]; int j2 = wsi[s][w];
            if (v2 > v || (v2 == v && j2 < j)) { v = v2; j = j2; }
        }
        g_samp[s * NPTS + i] = j;
    }
}

// ---------------- K4: triplet losses, one warp per pair ---------------------
__global__ __launch_bounds__(256) void k4_pairs(const float* __restrict__ x,
                                                const float* __restrict__ beta) {
    int wid  = threadIdx.x >> 5;
    int lane = threadIdx.x & 31;
    int pair = blockIdx.x * 8 + wid;          // < 57344
    int i = pair / 7;
    int s = pair - i * 7;
    int ii = i & 7;
    int p  = (i & ~7) + (s < ii ? s : s + 1); // positives in block order, self excluded
    int nn = g_samp[s * NPTS + i];            // samples.T.reshape(-1)

    const float4* xa = (const float4*)(x + (size_t)i  * DIM);
    const float4* xp = (const float4*)(x + (size_t)p  * DIM);
    const float4* xn = (const float4*)(x + (size_t)nn * DIM);
    float4 a = xa[lane], pv = xp[lane], nv = xn[lane];
    float dap = (a.x - pv.x) * (a.x - pv.x) + (a.y - pv.y) * (a.y - pv.y)
              + (a.z - pv.z) * (a.z - pv.z) + (a.w - pv.w) * (a.w - pv.w);
    float dan = (a.x - nv.x) * (a.x - nv.x) + (a.y - nv.y) * (a.y - nv.y)
              + (a.z - nv.z) * (a.z - nv.z) + (a.w - nv.w) * (a.w - nv.w);
    for (int off = 16; off; off >>= 1) {
        dap += __shfl_down_sync(0xffffffffu, dap, off);
        dan += __shfl_down_sync(0xffffffffu, dan, off);
    }

    __shared__ double sl[8];
    __shared__ float  sc[8];
    if (lane == 0) {
        float b    = beta[i];
        float d_ap = sqrtf(dap + 1e-8f);
        float d_an = sqrtf(dan + 1e-8f);
        float pos  = fmaxf(d_ap - b + 0.2f, 0.f);
        float neg  = fmaxf(b - d_an + 0.2f, 0.f);
        sl[wid] = (double)(pos + neg);
        sc[wid] = (pos > 0.f ? 1.f : 0.f) + (neg > 0.f ? 1.f : 0.f);
    }
    __syncthreads();
    if (threadIdx.x == 0) {
        double L = 0; float C = 0;
        for (int w = 0; w < 8; w++) { L += sl[w]; C += sc[w]; }
        g_ploss[blockIdx.x] = L;
        g_pcnt[blockIdx.x]  = C;
    }
}

// ---------------- K5: deterministic final reduction --------------------------
__global__ void k5_final(float* out) {
    __shared__ double sd[256];
    __shared__ float  scn[256];
    double L = 0; float C = 0;
    for (int idx = threadIdx.x; idx < NBLK4; idx += 256) {
        L += g_ploss[idx];
        C += g_pcnt[idx];
    }
    sd[threadIdx.x] = L; scn[threadIdx.x] = C;
    __syncthreads();
    for (int s = 128; s > 0; s >>= 1) {
        if (threadIdx.x < s) {
            sd[threadIdx.x]  += sd[threadIdx.x + s];
            scn[threadIdx.x] += scn[threadIdx.x + s];
        }
        __syncthreads();
    }
    if (threadIdx.x == 0) out[0] = (float)(sd[0] / (double)scn[0]);
}

// ---------------- launch (serial, proven R6 structure) -----------------------
extern "C" void kernel_launch(void* const* d_in, const int* in_sizes, int n_in,
                              void* d_out, int out_size) {
    const float* x    = (const float*)d_in[0];   // [8192,128] f32
    const float* beta = (const float*)d_in[2];   // [8192] f32 (d_in[1] = y, unused)

    cudaFuncSetAttribute(k1_fused, cudaFuncAttributeMaxDynamicSharedMemorySize, K1_SMEM);

    k0_sq<<<NPTS, 128>>>(x);
    dim3 g1(64, 64);
    k1_fused<<<g1, 256, K1_SMEM>>>(x);
    k3_sample<<<NPTS, 256>>>();
    k4_pairs<<<NBLK4, 256>>>(x, beta);
    k5_final<<<1, 256>>>((float*)d_out);
}